// round 3
// baseline (speedup 1.0000x reference)
#include <cuda_runtime.h>
#include <math.h>

#define S_LEN 512
#define B_SZ  64
#define HID   512
#define G3    1536
#define EMB_D 256
#define M_ROWS (S_LEN * B_SZ)   // 32768

typedef unsigned long long ull;

// ---------------- packed f32x2 helpers --------------------------------------
__device__ __forceinline__ ull pk2(float lo, float hi) {
    ull r; asm("mov.b64 %0, {%1,%2};" : "=l"(r) : "f"(lo), "f"(hi)); return r;
}
__device__ __forceinline__ ull dup2(float v) { return pk2(v, v); }
__device__ __forceinline__ void ffma2(ull& d, ull a, ull b) {
    asm("fma.rn.f32x2 %0, %1, %2, %0;" : "+l"(d) : "l"(a), "l"(b));
}
__device__ __forceinline__ float2 unpk2(ull v) {
    float2 f; asm("mov.b64 {%0,%1}, %2;" : "=f"(f.x), "=f"(f.y) : "l"(v)); return f;
}

// ---------------- scratch (static device globals; no allocation) ------------
__device__ float g_xemb[(size_t)M_ROWS * EMB_D];   // 32 MB
__device__ float g_xg  [(size_t)M_ROWS * G3];      // 192 MB
__device__ float g_ys  [(size_t)M_ROWS * HID];     // 64 MB
__device__ unsigned int g_flags[2][64];             // per-block step flags

// ---------------- embedding gather ------------------------------------------
__global__ void embed_kernel(const int* __restrict__ x,
                             const float* __restrict__ emb,
                             float* __restrict__ out) {
    int w    = (blockIdx.x << 3) + (threadIdx.x >> 5);  // row m = s*64+b
    int lane = threadIdx.x & 31;
    int s = w >> 6, b = w & 63;
    int tok = x[b * S_LEN + s];
    float4* dst = (float4*)(out + (size_t)w * EMB_D);
    if (tok == 0) {  // PAD_IDX row zeroed
        float4 z = make_float4(0.f, 0.f, 0.f, 0.f);
        dst[lane] = z; dst[lane + 32] = z;
    } else {
        const float4* src = (const float4*)(emb + (size_t)tok * EMB_D);
        dst[lane] = src[lane]; dst[lane + 32] = src[lane + 32];
    }
}

// ---------------- C[M,N] = A[M,K] @ W[N,K]^T + bias[N] ----------------------
// block tile 128x128, 256 threads, thread tile 8x8 (f32x2 packed), k-chunk 16
__global__ void __launch_bounds__(256, 2) gemm_bias_kernel(
    const float* __restrict__ A, const float* __restrict__ W,
    const float* __restrict__ bias, float* __restrict__ C,
    int M, int N, int K) {
    __shared__ float As[2][16][128];
    __shared__ float Bs[2][16][128];

    const int tid = threadIdx.x;
    const int n0 = blockIdx.x * 128;
    const int m0 = blockIdx.y * 128;
    const int tx = tid & 15, ty = tid >> 4;

    // acc2[p][j]: row-pair p (rows 2p,2p+1 of thread tile), col j
    ull acc2[4][8];
#pragma unroll
    for (int p = 0; p < 4; p++)
#pragma unroll
        for (int j = 0; j < 8; j++) acc2[p][j] = 0ULL;

    const int KT = K >> 4;

    // preload stage 0
#pragma unroll
    for (int i = 0; i < 2; i++) {
        int id = tid * 2 + i, row = id >> 2, kq = id & 3;
        float4 va = *(const float4*)(A + (size_t)(m0 + row) * K + kq * 4);
        float4 vb = *(const float4*)(W + (size_t)(n0 + row) * K + kq * 4);
        As[0][kq * 4 + 0][row] = va.x; As[0][kq * 4 + 1][row] = va.y;
        As[0][kq * 4 + 2][row] = va.z; As[0][kq * 4 + 3][row] = va.w;
        Bs[0][kq * 4 + 0][row] = vb.x; Bs[0][kq * 4 + 1][row] = vb.y;
        Bs[0][kq * 4 + 2][row] = vb.z; Bs[0][kq * 4 + 3][row] = vb.w;
    }
    __syncthreads();

    for (int kt = 0; kt < KT; ++kt) {
        const int cur = kt & 1;
        float4 pa[2], pb[2];
        const bool pf = (kt + 1) < KT;
        if (pf) {
#pragma unroll
            for (int i = 0; i < 2; i++) {
                int id = tid * 2 + i, row = id >> 2, kq = id & 3;
                pa[i] = *(const float4*)(A + (size_t)(m0 + row) * K + (kt + 1) * 16 + kq * 4);
                pb[i] = *(const float4*)(W + (size_t)(n0 + row) * K + (kt + 1) * 16 + kq * 4);
            }
        }
#pragma unroll
        for (int kk = 0; kk < 16; kk++) {
            // A pairs loaded directly as 64-bit (no pack MOVs)
            ull ap[4];
            ap[0] = *(const ull*)&As[cur][kk][ty * 4];
            ap[1] = *(const ull*)&As[cur][kk][ty * 4 + 2];
            ap[2] = *(const ull*)&As[cur][kk][64 + ty * 4];
            ap[3] = *(const ull*)&As[cur][kk][64 + ty * 4 + 2];
            float b[8];
            *(float4*)(b)     = *(const float4*)&Bs[cur][kk][tx * 4];
            *(float4*)(b + 4) = *(const float4*)&Bs[cur][kk][64 + tx * 4];
#pragma unroll
            for (int j = 0; j < 8; j++) {
                ull bd = dup2(b[j]);
#pragma unroll
                for (int p = 0; p < 4; p++) ffma2(acc2[p][j], ap[p], bd);
            }
        }
        if (pf) {
            const int nxt = cur ^ 1;
#pragma unroll
            for (int i = 0; i < 2; i++) {
                int id = tid * 2 + i, row = id >> 2, kq = id & 3;
                As[nxt][kq * 4 + 0][row] = pa[i].x; As[nxt][kq * 4 + 1][row] = pa[i].y;
                As[nxt][kq * 4 + 2][row] = pa[i].z; As[nxt][kq * 4 + 3][row] = pa[i].w;
                Bs[nxt][kq * 4 + 0][row] = pb[i].x; Bs[nxt][kq * 4 + 1][row] = pb[i].y;
                Bs[nxt][kq * 4 + 2][row] = pb[i].z; Bs[nxt][kq * 4 + 3][row] = pb[i].w;
            }
        }
        __syncthreads();
    }

    float4 bb0 = *(const float4*)&bias[n0 + tx * 4];
    float4 bb1 = *(const float4*)&bias[n0 + 64 + tx * 4];
#pragma unroll
    for (int p = 0; p < 4; p++) {
        float2 c[8];
#pragma unroll
        for (int j = 0; j < 8; j++) c[j] = unpk2(acc2[p][j]);
#pragma unroll
        for (int half = 0; half < 2; half++) {
            int i = 2 * p + half;
            int m = m0 + ((i < 4) ? (ty * 4 + i) : (64 + ty * 4 + i - 4));
            float e[8];
#pragma unroll
            for (int j = 0; j < 8; j++) e[j] = half ? c[j].y : c[j].x;
            float4 v0 = make_float4(e[0] + bb0.x, e[1] + bb0.y,
                                    e[2] + bb0.z, e[3] + bb0.w);
            float4 v1 = make_float4(e[4] + bb1.x, e[5] + bb1.y,
                                    e[6] + bb1.z, e[7] + bb1.w);
            *(float4*)(C + (size_t)m * N + n0 + tx * 4)      = v0;
            *(float4*)(C + (size_t)m * N + n0 + 64 + tx * 4) = v1;
        }
    }
}

// ---------------- GRU recurrence (persistent, 128 blocks, 2 batch groups) ---
// block (bg, dg): bg = bid&1 -> rows [bg*32, +32); dg = bid>>1 -> dims [dg*8, +8)
// smem: Wsh [512][24] (k-major), hsh [512][32] xor-swizzled by (k>>2)&31,
//       part[8 kgroups][256 rowdim][4]
#define GRU_SMEM_FLOATS (512 * 24 + 512 * 32 + 8 * 256 * 4)
#define GRU_SMEM_BYTES  (GRU_SMEM_FLOATS * 4)

__device__ __forceinline__ unsigned ld_acq(const unsigned* p) {
    unsigned v;
    asm volatile("ld.global.acquire.gpu.u32 %0, [%1];" : "=r"(v) : "l"(p) : "memory");
    return v;
}
__device__ __forceinline__ void st_rel(unsigned* p, unsigned v) {
    asm volatile("st.global.release.gpu.u32 [%0], %1;" :: "l"(p), "r"(v) : "memory");
}

__global__ void __launch_bounds__(256, 1) gru_kernel(
    const float* __restrict__ xg,    // [S][64][1536]
    const float* __restrict__ Whh,   // [1536][512]
    const float* __restrict__ bhh,   // [1536]
    float* __restrict__ ys)          // [S][64][512]
{
    extern __shared__ float sm[];
    float* Wsh  = sm;                  // 12288
    float* hsh  = sm + 512 * 24;       // 16384
    float* part = hsh + 512 * 32;      // 8192
    __shared__ unsigned sh_base;

    const int tid = threadIdx.x;
    const int bg  = blockIdx.x & 1;
    const int dg  = blockIdx.x >> 1;
    const int rowBase = bg * 32;
    const int dimBase = dg * 8;

    if (tid == 0) sh_base = *(volatile unsigned*)&g_flags[bg][dg];

    // load W_hh slice (24 gate rows) into smem, k-major
    for (int idx = tid; idx < 24 * 512; idx += 256) {
        int col = idx >> 9;       // 0..23
        int k   = idx & 511;
        int dl = col / 3, g = col % 3;
        int grow = g * 512 + dimBase + dl;
        Wsh[k * 24 + col] = Whh[(size_t)grow * 512 + k];
    }

    // gating role: one thread per (row, dim)
    const int myrow = tid >> 3;           // 0..31
    const int mydl  = tid & 7;            // 0..7
    const int mydim = dimBase + mydl;
    const float b_r = bhh[mydim];
    const float b_z = bhh[512 + mydim];
    const float b_n = bhh[1024 + mydim];

    // compute role: split-k over 8 warps, thread tile 4 rows x 2 dims x 3 gates
    const int kg  = tid >> 5;             // warp = k-group (64 k each)
    const int pos = tid & 31;
    const int rg  = pos >> 2;             // 0..7  -> rows rg*4..+3
    const int dgi = pos & 3;              // 0..3  -> dims dgi*2, dgi*2+1

    __syncthreads();
    const unsigned base = sh_base;

    for (int t = 0; t < S_LEN; ++t) {
        // prefetch xg for gating (consumed after the GEMM)
        size_t xbase = ((size_t)t * 64 + rowBase + myrow) * G3 + mydim;
        float xr = xg[xbase], xz = xg[xbase + 512], xn = xg[xbase + 1024];

        if (t == 0) {
            for (int idx = tid; idx < 512 * 32; idx += 256) hsh[idx] = 0.f;
        } else {
            // wait for all 64 producer blocks of this batch group (flag >= base+t)
            if (tid < 64) {
                const unsigned target = base + (unsigned)t;
                const unsigned* fp = &g_flags[bg][tid];
                while ((int)(ld_acq(fp) - target) < 0) { }
            }
            __syncthreads();
            // load h(t-1): 16 independent LDG.128 (MLP=16), then swizzled STS
            const float4* hsrc4 = (const float4*)(ys + ((size_t)(t - 1) * 64 + rowBase) * HID);
            float4 v[16];
#pragma unroll
            for (int i = 0; i < 16; i++) v[i] = __ldcg(hsrc4 + tid + 256 * i);
#pragma unroll
            for (int i = 0; i < 16; i++) {
                int q = tid + 256 * i;
                int r = q >> 7, k4 = (q & 127) << 2;
                int sw = (k4 >> 2) & 31;   // same for k4..k4+3
                hsh[(k4 + 0) * 32 + (r ^ sw)] = v[i].x;
                hsh[(k4 + 1) * 32 + (r ^ sw)] = v[i].y;
                hsh[(k4 + 2) * 32 + (r ^ sw)] = v[i].z;
                hsh[(k4 + 3) * 32 + (r ^ sw)] = v[i].w;
            }
        }
        __syncthreads();

        // hg partials: acc2[r(4 rows)][p(3 gate-dim pairs)]
        ull acc2[12];
#pragma unroll
        for (int i = 0; i < 12; i++) acc2[i] = 0ULL;
        const int k0 = kg * 64;
        const float* Wp = Wsh + dgi * 6;
        const int rbase = rg * 4;
#pragma unroll 4
        for (int k = k0; k < k0 + 64; ++k) {
            const float* wk = Wp + k * 24;
            ull w01 = *(const ull*)(wk);
            ull w23 = *(const ull*)(wk + 2);
            ull w45 = *(const ull*)(wk + 4);
            const int ksw = (k >> 2) & 31;
            const float* hk = hsh + k * 32;
            ull h0 = dup2(hk[(rbase + 0) ^ ksw]);
            ull h1 = dup2(hk[(rbase + 1) ^ ksw]);
            ull h2 = dup2(hk[(rbase + 2) ^ ksw]);
            ull h3 = dup2(hk[(rbase + 3) ^ ksw]);
            ffma2(acc2[0],  h0, w01); ffma2(acc2[1],  h0, w23); ffma2(acc2[2],  h0, w45);
            ffma2(acc2[3],  h1, w01); ffma2(acc2[4],  h1, w23); ffma2(acc2[5],  h1, w45);
            ffma2(acc2[6],  h2, w01); ffma2(acc2[7],  h2, w23); ffma2(acc2[8],  h2, w45);
            ffma2(acc2[9],  h3, w01); ffma2(acc2[10], h3, w23); ffma2(acc2[11], h3, w45);
        }
        // write partials: pairs = (j0g0,j0g1),(j0g2,j1g0),(j1g1,j1g2)
#pragma unroll
        for (int i = 0; i < 4; i++) {
            float2 v0 = unpk2(acc2[i * 3 + 0]);
            float2 v1 = unpk2(acc2[i * 3 + 1]);
            float2 v2 = unpk2(acc2[i * 3 + 2]);
            int rd0 = (rbase + i) * 8 + dgi * 2;
            *(float4*)(part + (kg * 256 + rd0) * 4)
                = make_float4(v0.x, v0.y, v1.x, 0.f);
            *(float4*)(part + (kg * 256 + rd0 + 1) * 4)
                = make_float4(v1.y, v2.x, v2.y, 0.f);
        }
        __syncthreads();

        // reduce 8 k-groups + gates, one thread per (row, dim)
        float hr = b_r, hz = b_z, hn = b_n;
#pragma unroll
        for (int kk = 0; kk < 8; kk++) {
            float4 p = *(const float4*)(part + (kk * 256 + tid) * 4);
            hr += p.x; hz += p.y; hn += p.z;
        }
        float h_old = hsh[mydim * 32 + (myrow ^ ((mydim >> 2) & 31))];
        // fast, saturation-safe gates
        float er = __expf(-(xr + hr));
        float rr = __fdividef(1.f, 1.f + er);
        float ez = __expf(-(xz + hz));
        float zz = __fdividef(1.f, 1.f + ez);
        float an = xn + rr * hn;
        float e2 = __expf(2.f * an);
        float nn = 1.f - __fdividef(2.f, e2 + 1.f);   // tanh(an)
        float hnew = (1.f - zz) * nn + zz * h_old;
        ys[((size_t)t * 64 + rowBase + myrow) * HID + mydim] = hnew;

        __threadfence();
        __syncthreads();
        if (tid == 0) st_rel(&g_flags[bg][dg], base + (unsigned)t + 1u);
    }
}

// ---------------- final FC + sigmoid ----------------------------------------
__global__ void fc_kernel(const float* __restrict__ ys,
                          const float* __restrict__ Wfc,
                          const float* __restrict__ bfc,
                          float* __restrict__ out) {
    int b = blockIdx.x, tid = threadIdx.x;  // 128 threads
    const float* h = ys + ((size_t)(S_LEN - 1) * 64 + b) * HID;
    float s = 0.f;
    for (int i = tid; i < HID; i += 128) s += h[i] * Wfc[i];
#pragma unroll
    for (int o = 16; o; o >>= 1) s += __shfl_down_sync(0xffffffffu, s, o);
    __shared__ float ps[4];
    if ((tid & 31) == 0) ps[tid >> 5] = s;
    __syncthreads();
    if (tid == 0) {
        float v = ps[0] + ps[1] + ps[2] + ps[3] + bfc[0];
        out[b] = 1.f / (1.f + expf(-v));
    }
}

// ---------------- launch ----------------------------------------------------
extern "C" void kernel_launch(void* const* d_in, const int* in_sizes, int n_in,
                              void* d_out, int out_size) {
    (void)in_sizes; (void)n_in; (void)out_size;
    const int*   x    = (const int*)  d_in[0];
    const float* emb  = (const float*)d_in[1];
    const float* Wih0 = (const float*)d_in[2];
    const float* Whh0 = (const float*)d_in[3];
    const float* bih0 = (const float*)d_in[4];
    const float* bhh0 = (const float*)d_in[5];
    const float* Wih1 = (const float*)d_in[6];
    const float* Whh1 = (const float*)d_in[7];
    const float* bih1 = (const float*)d_in[8];
    const float* bhh1 = (const float*)d_in[9];
    const float* Wfc  = (const float*)d_in[10];
    const float* bfc  = (const float*)d_in[11];
    float* out = (float*)d_out;

    float *xemb, *xgbuf, *ysbuf;
    cudaGetSymbolAddress((void**)&xemb,  g_xemb);
    cudaGetSymbolAddress((void**)&xgbuf, g_xg);
    cudaGetSymbolAddress((void**)&ysbuf, g_ys);

    cudaFuncSetAttribute(gru_kernel, cudaFuncAttributeMaxDynamicSharedMemorySize,
                         GRU_SMEM_BYTES);

    embed_kernel<<<4096, 256>>>(x, emb, xemb);
    gemm_bias_kernel<<<dim3(G3 / 128, M_ROWS / 128), 256>>>(
        xemb, Wih0, bih0, xgbuf, M_ROWS, G3, EMB_D);
    gru_kernel<<<128, 256, GRU_SMEM_BYTES>>>(xgbuf, Whh0, bhh0, ysbuf);
    gemm_bias_kernel<<<dim3(G3 / 128, M_ROWS / 128), 256>>>(
        ysbuf, Wih1, bih1, xgbuf, M_ROWS, G3, HID);
    gru_kernel<<<128, 256, GRU_SMEM_BYTES>>>(xgbuf, Whh1, bhh1, ysbuf);
    fc_kernel<<<64, 128>>>(ysbuf, Wfc, bfc, out);
}

// round 4
// speedup vs baseline: 1.3229x; 1.3229x over previous
#include <cuda_runtime.h>
#include <math.h>

#define S_LEN 512
#define B_SZ  64
#define HID   512
#define G3    1536
#define EMB_D 256
#define M_ROWS (S_LEN * B_SZ)   // 32768

typedef unsigned long long ull;

// ---------------- packed f32x2 helpers --------------------------------------
__device__ __forceinline__ ull pk2(float lo, float hi) {
    ull r; asm("mov.b64 %0, {%1,%2};" : "=l"(r) : "f"(lo), "f"(hi)); return r;
}
__device__ __forceinline__ ull dup2(float v) { return pk2(v, v); }
__device__ __forceinline__ void ffma2(ull& d, ull a, ull b) {
    asm("fma.rn.f32x2 %0, %1, %2, %0;" : "+l"(d) : "l"(a), "l"(b));
}
__device__ __forceinline__ float2 unpk2(ull v) {
    float2 f; asm("mov.b64 {%0,%1}, %2;" : "=f"(f.x), "=f"(f.y) : "l"(v)); return f;
}

// ---------------- scratch (static device globals; no allocation) ------------
__device__ float g_xemb[(size_t)M_ROWS * EMB_D];   // 32 MB
__device__ float g_xg  [(size_t)M_ROWS * G3];      // 192 MB
__device__ float g_ys  [(size_t)M_ROWS * HID];     // 64 MB
// one flag per producer block, PADDED to a full 128B L2 line each so polling
// traffic spreads across LTS slices instead of hammering two lines
__device__ unsigned int g_flags[2][64][32];

// ---------------- embedding gather ------------------------------------------
__global__ void embed_kernel(const int* __restrict__ x,
                             const float* __restrict__ emb,
                             float* __restrict__ out) {
    int w    = (blockIdx.x << 3) + (threadIdx.x >> 5);  // row m = s*64+b
    int lane = threadIdx.x & 31;
    int s = w >> 6, b = w & 63;
    int tok = x[b * S_LEN + s];
    float4* dst = (float4*)(out + (size_t)w * EMB_D);
    if (tok == 0) {  // PAD_IDX row zeroed
        float4 z = make_float4(0.f, 0.f, 0.f, 0.f);
        dst[lane] = z; dst[lane + 32] = z;
    } else {
        const float4* src = (const float4*)(emb + (size_t)tok * EMB_D);
        dst[lane] = src[lane]; dst[lane + 32] = src[lane + 32];
    }
}

// ---------------- C[M,N] = A[M,K] @ W[N,K]^T + bias[N] ----------------------
// block tile 128x128, 256 threads, thread tile 8x8 (f32x2 packed), k-chunk 16
__global__ void __launch_bounds__(256, 2) gemm_bias_kernel(
    const float* __restrict__ A, const float* __restrict__ W,
    const float* __restrict__ bias, float* __restrict__ C,
    int M, int N, int K) {
    __shared__ float As[2][16][128];
    __shared__ float Bs[2][16][128];

    const int tid = threadIdx.x;
    const int n0 = blockIdx.x * 128;
    const int m0 = blockIdx.y * 128;
    const int tx = tid & 15, ty = tid >> 4;

    ull acc2[4][8];
#pragma unroll
    for (int p = 0; p < 4; p++)
#pragma unroll
        for (int j = 0; j < 8; j++) acc2[p][j] = 0ULL;

    const int KT = K >> 4;

    // preload stage 0
#pragma unroll
    for (int i = 0; i < 2; i++) {
        int id = tid * 2 + i, row = id >> 2, kq = id & 3;
        float4 va = *(const float4*)(A + (size_t)(m0 + row) * K + kq * 4);
        float4 vb = *(const float4*)(W + (size_t)(n0 + row) * K + kq * 4);
        As[0][kq * 4 + 0][row] = va.x; As[0][kq * 4 + 1][row] = va.y;
        As[0][kq * 4 + 2][row] = va.z; As[0][kq * 4 + 3][row] = va.w;
        Bs[0][kq * 4 + 0][row] = vb.x; Bs[0][kq * 4 + 1][row] = vb.y;
        Bs[0][kq * 4 + 2][row] = vb.z; Bs[0][kq * 4 + 3][row] = vb.w;
    }
    __syncthreads();

    for (int kt = 0; kt < KT; ++kt) {
        const int cur = kt & 1;
        float4 pa[2], pb[2];
        const bool pf = (kt + 1) < KT;
        if (pf) {
#pragma unroll
            for (int i = 0; i < 2; i++) {
                int id = tid * 2 + i, row = id >> 2, kq = id & 3;
                pa[i] = *(const float4*)(A + (size_t)(m0 + row) * K + (kt + 1) * 16 + kq * 4);
                pb[i] = *(const float4*)(W + (size_t)(n0 + row) * K + (kt + 1) * 16 + kq * 4);
            }
        }
#pragma unroll
        for (int kk = 0; kk < 16; kk++) {
            ull ap[4];
            ap[0] = *(const ull*)&As[cur][kk][ty * 4];
            ap[1] = *(const ull*)&As[cur][kk][ty * 4 + 2];
            ap[2] = *(const ull*)&As[cur][kk][64 + ty * 4];
            ap[3] = *(const ull*)&As[cur][kk][64 + ty * 4 + 2];
            float b[8];
            *(float4*)(b)     = *(const float4*)&Bs[cur][kk][tx * 4];
            *(float4*)(b + 4) = *(const float4*)&Bs[cur][kk][64 + tx * 4];
#pragma unroll
            for (int j = 0; j < 8; j++) {
                ull bd = dup2(b[j]);
#pragma unroll
                for (int p = 0; p < 4; p++) ffma2(acc2[p][j], ap[p], bd);
            }
        }
        if (pf) {
            const int nxt = cur ^ 1;
#pragma unroll
            for (int i = 0; i < 2; i++) {
                int id = tid * 2 + i, row = id >> 2, kq = id & 3;
                As[nxt][kq * 4 + 0][row] = pa[i].x; As[nxt][kq * 4 + 1][row] = pa[i].y;
                As[nxt][kq * 4 + 2][row] = pa[i].z; As[nxt][kq * 4 + 3][row] = pa[i].w;
                Bs[nxt][kq * 4 + 0][row] = pb[i].x; Bs[nxt][kq * 4 + 1][row] = pb[i].y;
                Bs[nxt][kq * 4 + 2][row] = pb[i].z; Bs[nxt][kq * 4 + 3][row] = pb[i].w;
            }
        }
        __syncthreads();
    }

    float4 bb0 = *(const float4*)&bias[n0 + tx * 4];
    float4 bb1 = *(const float4*)&bias[n0 + 64 + tx * 4];
#pragma unroll
    for (int p = 0; p < 4; p++) {
        float2 c[8];
#pragma unroll
        for (int j = 0; j < 8; j++) c[j] = unpk2(acc2[p][j]);
#pragma unroll
        for (int half = 0; half < 2; half++) {
            int i = 2 * p + half;
            int m = m0 + ((i < 4) ? (ty * 4 + i) : (64 + ty * 4 + i - 4));
            float e[8];
#pragma unroll
            for (int j = 0; j < 8; j++) e[j] = half ? c[j].y : c[j].x;
            float4 v0 = make_float4(e[0] + bb0.x, e[1] + bb0.y,
                                    e[2] + bb0.z, e[3] + bb0.w);
            float4 v1 = make_float4(e[4] + bb1.x, e[5] + bb1.y,
                                    e[6] + bb1.z, e[7] + bb1.w);
            *(float4*)(C + (size_t)m * N + n0 + tx * 4)      = v0;
            *(float4*)(C + (size_t)m * N + n0 + 64 + tx * 4) = v1;
        }
    }
}

// ---------------- GRU recurrence (persistent, 128 blocks, 2 batch groups) ---
#define GRU_SMEM_FLOATS (512 * 24 + 512 * 32 + 8 * 256 * 4)
#define GRU_SMEM_BYTES  (GRU_SMEM_FLOATS * 4)

__device__ __forceinline__ unsigned ld_acq(const unsigned* p) {
    unsigned v;
    asm volatile("ld.global.acquire.gpu.u32 %0, [%1];" : "=r"(v) : "l"(p) : "memory");
    return v;
}
__device__ __forceinline__ void st_rel(unsigned* p, unsigned v) {
    asm volatile("st.global.release.gpu.u32 [%0], %1;" :: "l"(p), "r"(v) : "memory");
}

__global__ void __launch_bounds__(256, 1) gru_kernel(
    const float* __restrict__ xg,    // [S][64][1536]
    const float* __restrict__ Whh,   // [1536][512]
    const float* __restrict__ bhh,   // [1536]
    float* __restrict__ ys)          // [S][64][512]
{
    extern __shared__ float sm[];
    float* Wsh  = sm;                  // 12288
    float* hsh  = sm + 512 * 24;       // 16384
    float* part = hsh + 512 * 32;      // 8192
    __shared__ unsigned sh_base;

    const int tid = threadIdx.x;
    const int bg  = blockIdx.x & 1;
    const int dg  = blockIdx.x >> 1;
    const int rowBase = bg * 32;
    const int dimBase = dg * 8;

    if (tid == 0) sh_base = *(volatile unsigned*)&g_flags[bg][dg][0];

    // load W_hh slice (24 gate rows) into smem, k-major
    for (int idx = tid; idx < 24 * 512; idx += 256) {
        int col = idx >> 9;       // 0..23
        int k   = idx & 511;
        int dl = col / 3, g = col % 3;
        int grow = g * 512 + dimBase + dl;
        Wsh[k * 24 + col] = Whh[(size_t)grow * 512 + k];
    }

    // gating role: one thread per (row, dim)
    const int myrow = tid >> 3;           // 0..31
    const int mydl  = tid & 7;            // 0..7
    const int mydim = dimBase + mydl;
    const float b_r = bhh[mydim];
    const float b_z = bhh[512 + mydim];
    const float b_n = bhh[1024 + mydim];

    // compute role: split-k over 8 warps, thread tile 4 rows x 2 dims x 3 gates
    const int kg  = tid >> 5;             // warp = k-group (64 k each)
    const int pos = tid & 31;
    const int rg  = pos >> 2;             // 0..7  -> rows rg*4..+3
    const int dgi = pos & 3;              // 0..3  -> dims dgi*2, dgi*2+1

    __syncthreads();
    const unsigned base = sh_base;

    for (int t = 0; t < S_LEN; ++t) {
        // prefetch xg for gating (consumed after the GEMM)
        size_t xbase = ((size_t)t * 64 + rowBase + myrow) * G3 + mydim;
        float xr = xg[xbase], xz = xg[xbase + 512], xn = xg[xbase + 1024];

        if (t == 0) {
            for (int idx = tid; idx < 512 * 32; idx += 256) hsh[idx] = 0.f;
        } else {
            // wait for all 64 producer blocks (each flag on its own 128B line)
            if (tid < 64) {
                const unsigned target = base + (unsigned)t;
                const unsigned* fp = &g_flags[bg][tid][0];
                while ((int)(ld_acq(fp) - target) < 0) { }
            }
            __syncthreads();
            // load h(t-1): 16 independent LDG.128 (MLP=16), then swizzled STS
            const float4* hsrc4 = (const float4*)(ys + ((size_t)(t - 1) * 64 + rowBase) * HID);
            float4 v[16];
#pragma unroll
            for (int i = 0; i < 16; i++) v[i] = __ldcg(hsrc4 + tid + 256 * i);
#pragma unroll
            for (int i = 0; i < 16; i++) {
                int q = tid + 256 * i;
                int r = q >> 7, k4 = (q & 127) << 2;
                int sw = (k4 >> 2) & 31;   // same for k4..k4+3
                hsh[(k4 + 0) * 32 + (r ^ sw)] = v[i].x;
                hsh[(k4 + 1) * 32 + (r ^ sw)] = v[i].y;
                hsh[(k4 + 2) * 32 + (r ^ sw)] = v[i].z;
                hsh[(k4 + 3) * 32 + (r ^ sw)] = v[i].w;
            }
        }
        __syncthreads();

        // hg partials: acc2[r(4 rows)][p(3 gate-dim pairs)]
        ull acc2[12];
#pragma unroll
        for (int i = 0; i < 12; i++) acc2[i] = 0ULL;
        const int k0 = kg * 64;
        const float* Wp = Wsh + dgi * 6;
        const int rbase = rg * 4;
#pragma unroll 4
        for (int k = k0; k < k0 + 64; ++k) {
            const float* wk = Wp + k * 24;
            ull w01 = *(const ull*)(wk);
            ull w23 = *(const ull*)(wk + 2);
            ull w45 = *(const ull*)(wk + 4);
            const int ksw = (k >> 2) & 31;
            const float* hk = hsh + k * 32;
            ull h0 = dup2(hk[(rbase + 0) ^ ksw]);
            ull h1 = dup2(hk[(rbase + 1) ^ ksw]);
            ull h2 = dup2(hk[(rbase + 2) ^ ksw]);
            ull h3 = dup2(hk[(rbase + 3) ^ ksw]);
            ffma2(acc2[0],  h0, w01); ffma2(acc2[1],  h0, w23); ffma2(acc2[2],  h0, w45);
            ffma2(acc2[3],  h1, w01); ffma2(acc2[4],  h1, w23); ffma2(acc2[5],  h1, w45);
            ffma2(acc2[6],  h2, w01); ffma2(acc2[7],  h2, w23); ffma2(acc2[8],  h2, w45);
            ffma2(acc2[9],  h3, w01); ffma2(acc2[10], h3, w23); ffma2(acc2[11], h3, w45);
        }
        // write partials: pairs = (j0g0,j0g1),(j0g2,j1g0),(j1g1,j1g2)
#pragma unroll
        for (int i = 0; i < 4; i++) {
            float2 v0 = unpk2(acc2[i * 3 + 0]);
            float2 v1 = unpk2(acc2[i * 3 + 1]);
            float2 v2 = unpk2(acc2[i * 3 + 2]);
            int rd0 = (rbase + i) * 8 + dgi * 2;
            *(float4*)(part + (kg * 256 + rd0) * 4)
                = make_float4(v0.x, v0.y, v1.x, 0.f);
            *(float4*)(part + (kg * 256 + rd0 + 1) * 4)
                = make_float4(v1.y, v2.x, v2.y, 0.f);
        }
        __syncthreads();

        // reduce 8 k-groups + gates, one thread per (row, dim)
        float hr = b_r, hz = b_z, hn = b_n;
#pragma unroll
        for (int kk = 0; kk < 8; kk++) {
            float4 p = *(const float4*)(part + (kk * 256 + tid) * 4);
            hr += p.x; hz += p.y; hn += p.z;
        }
        float h_old = hsh[mydim * 32 + (myrow ^ ((mydim >> 2) & 31))];
        // fast, saturation-safe gates
        float er = __expf(-(xr + hr));
        float rr = __fdividef(1.f, 1.f + er);
        float ez = __expf(-(xz + hz));
        float zz = __fdividef(1.f, 1.f + ez);
        float an = xn + rr * hn;
        float e2 = __expf(2.f * an);
        float nn = 1.f - __fdividef(2.f, e2 + 1.f);   // tanh(an)
        float hnew = (1.f - zz) * nn + zz * h_old;
        ys[((size_t)t * 64 + rowBase + myrow) * HID + mydim] = hnew;

        __threadfence();
        __syncthreads();
        if (tid == 0) st_rel(&g_flags[bg][dg][0], base + (unsigned)t + 1u);
    }
}

// ---------------- final FC + sigmoid ----------------------------------------
__global__ void fc_kernel(const float* __restrict__ ys,
                          const float* __restrict__ Wfc,
                          const float* __restrict__ bfc,
                          float* __restrict__ out) {
    int b = blockIdx.x, tid = threadIdx.x;  // 128 threads
    const float* h = ys + ((size_t)(S_LEN - 1) * 64 + b) * HID;
    float s = 0.f;
    for (int i = tid; i < HID; i += 128) s += h[i] * Wfc[i];
#pragma unroll
    for (int o = 16; o; o >>= 1) s += __shfl_down_sync(0xffffffffu, s, o);
    __shared__ float ps[4];
    if ((tid & 31) == 0) ps[tid >> 5] = s;
    __syncthreads();
    if (tid == 0) {
        float v = ps[0] + ps[1] + ps[2] + ps[3] + bfc[0];
        out[b] = 1.f / (1.f + expf(-v));
    }
}

// ---------------- launch ----------------------------------------------------
extern "C" void kernel_launch(void* const* d_in, const int* in_sizes, int n_in,
                              void* d_out, int out_size) {
    (void)in_sizes; (void)n_in; (void)out_size;
    const int*   x    = (const int*)  d_in[0];
    const float* emb  = (const float*)d_in[1];
    const float* Wih0 = (const float*)d_in[2];
    const float* Whh0 = (const float*)d_in[3];
    const float* bih0 = (const float*)d_in[4];
    const float* bhh0 = (const float*)d_in[5];
    const float* Wih1 = (const float*)d_in[6];
    const float* Whh1 = (const float*)d_in[7];
    const float* bih1 = (const float*)d_in[8];
    const float* bhh1 = (const float*)d_in[9];
    const float* Wfc  = (const float*)d_in[10];
    const float* bfc  = (const float*)d_in[11];
    float* out = (float*)d_out;

    float *xemb, *xgbuf, *ysbuf;
    cudaGetSymbolAddress((void**)&xemb,  g_xemb);
    cudaGetSymbolAddress((void**)&xgbuf, g_xg);
    cudaGetSymbolAddress((void**)&ysbuf, g_ys);

    cudaFuncSetAttribute(gru_kernel, cudaFuncAttributeMaxDynamicSharedMemorySize,
                         GRU_SMEM_BYTES);

    embed_kernel<<<4096, 256>>>(x, emb, xemb);
    gemm_bias_kernel<<<dim3(G3 / 128, M_ROWS / 128), 256>>>(
        xemb, Wih0, bih0, xgbuf, M_ROWS, G3, EMB_D);
    gru_kernel<<<128, 256, GRU_SMEM_BYTES>>>(xgbuf, Whh0, bhh0, ysbuf);
    gemm_bias_kernel<<<dim3(G3 / 128, M_ROWS / 128), 256>>>(
        ysbuf, Wih1, bih1, xgbuf, M_ROWS, G3, HID);
    gru_kernel<<<128, 256, GRU_SMEM_BYTES>>>(xgbuf, Whh1, bhh1, ysbuf);
    fc_kernel<<<64, 128>>>(ysbuf, Wfc, bfc, out);
}